// round 16
// baseline (speedup 1.0000x reference)
#include <cuda_runtime.h>
#include <cuda_bf16.h>
#include <cstdint>

// DCT per 8x8 patch: out(N,64) = X(N,64) @ K(64,64) — GEMM on the tensor pipe
// via mma.sync (sm_80+ PTX; tcgen05 unavailable: harness targets sm_103).
// bf16 3-term split: D = Xh*Kh + Xh*Kl + Xl*Kh  (err ~2^-17).
// Per CTA: 128 strips (M=128), N=64, K=64; each warp does M=32.

#define THREADS     128
#define TILE_STRIPS 128
#define TILE_F4     (TILE_STRIPS * 16)

// static smem layout (bytes), 48KB total, 1024-aligned base
#define SM_A_HI  0          // 128 rows x 128B (SW128)
#define SM_A_LO  16384
#define SM_B_HI  32768      // 64 rows x 128B
#define SM_B_LO  40960
#define SM_SIZE  49152
#define SM_STAGE 0          // output staging (34816B) reuses A+B after barrier

#define SW128(o) ((o) ^ (((o) >> 3) & 0x70))

static __device__ __align__(16) __nv_bfloat16 g_Bhi[64 * 64];  // [n][k] = Kmat[k][n]
static __device__ __align__(16) __nv_bfloat16 g_Blo[64 * 64];

__device__ __forceinline__ uint32_t smem_u32(const void* p) {
    uint32_t a;
    asm("{ .reg .u64 t; cvta.to.shared.u64 t, %1; cvt.u32.u64 %0, t; }" : "=r"(a) : "l"(p));
    return a;
}
__device__ __forceinline__ uint32_t pack_bf16x2(float x0, float x1) {  // x0 -> low
    uint32_t r;
    asm("cvt.rn.bf16x2.f32 %0, %1, %2;" : "=r"(r) : "f"(x1), "f"(x0));
    return r;
}
__device__ __forceinline__ uint32_t pack_lo(float x0, float x1, uint32_t hi2) {
    float h0 = __uint_as_float(hi2 << 16);
    float h1 = __uint_as_float(hi2 & 0xFFFF0000u);
    return pack_bf16x2(x0 - h0, x1 - h1);
}
__device__ __forceinline__ void ldm4(uint32_t* r, uint32_t addr) {
    asm volatile("ldmatrix.sync.aligned.m8n8.x4.shared.b16 {%0,%1,%2,%3}, [%4];"
                 : "=r"(r[0]), "=r"(r[1]), "=r"(r[2]), "=r"(r[3]) : "r"(addr));
}
__device__ __forceinline__ void mma16816(float* d, const uint32_t* a,
                                         uint32_t b0, uint32_t b1) {
    asm volatile(
        "mma.sync.aligned.m16n8k16.row.col.f32.bf16.bf16.f32 "
        "{%0,%1,%2,%3}, {%4,%5,%6,%7}, {%8,%9}, {%0,%1,%2,%3};"
        : "+f"(d[0]), "+f"(d[1]), "+f"(d[2]), "+f"(d[3])
        : "r"(a[0]), "r"(a[1]), "r"(a[2]), "r"(a[3]), "r"(b0), "r"(b1));
}

// ---- prep: Kmat fp32 (64x64, [k][n]) -> bf16 hi/lo transposed [n][k] ----
__global__ void prep_B_kernel(const float* __restrict__ Kmat)
{
    int i = blockIdx.x * blockDim.x + threadIdx.x;
    if (i >= 4096) return;
    int n = i >> 6, k = i & 63;
    float v = Kmat[k * 64 + n];
    __nv_bfloat16 h = __float2bfloat16(v);
    g_Bhi[i] = h;
    g_Blo[i] = __float2bfloat16(v - __bfloat162float(h));
}

__global__ __launch_bounds__(THREADS)
void dct_mma_kernel(const float4* __restrict__ in4, float4* __restrict__ out4)
{
    __shared__ __align__(1024) char smem[SM_SIZE];
    const uint32_t sb = smem_u32(smem);
    const int t = threadIdx.x, wid = t >> 5, lane = t & 31;

    const size_t base = (size_t)blockIdx.x * TILE_F4;

    // ---- Phase 1: X tile -> bf16 hi/lo, SW128 smem ----
#pragma unroll
    for (int k = 0; k < 16; ++k) {
        float4 v = in4[base + k * THREADS + t];
        int s = 8 * k + (t >> 4);        // strip row
        int c = t & 15;                  // 4-float chunk -> 8 bytes bf16
        uint32_t h01 = pack_bf16x2(v.x, v.y);
        uint32_t h23 = pack_bf16x2(v.z, v.w);
        uint32_t l01 = pack_lo(v.x, v.y, h01);
        uint32_t l23 = pack_lo(v.z, v.w, h23);
        uint32_t off = SW128((uint32_t)(s * 128 + c * 8));
        *(uint2*)(smem + SM_A_HI + off) = make_uint2(h01, h23);
        *(uint2*)(smem + SM_A_LO + off) = make_uint2(l01, l23);
    }
    // B hi/lo: 512 float4 each, 4 per thread, SW128 rows of 128B
    {
        const float4* bh = (const float4*)g_Bhi;
        const float4* bl = (const float4*)g_Blo;
#pragma unroll
        for (int i = 0; i < 4; ++i) {
            int idx = i * THREADS + t;
            int n = idx >> 3, cb = (idx & 7) * 16;
            uint32_t off = SW128((uint32_t)(n * 128 + cb));
            *(float4*)(smem + SM_B_HI + off) = bh[idx];
            *(float4*)(smem + SM_B_LO + off) = bl[idx];
        }
    }
    __syncthreads();

    // ---- Phase 2: per-warp MMA, M=32 rows (strips wid*32..+31) ----
    float acc[16][4];
#pragma unroll
    for (int f = 0; f < 16; ++f)
#pragma unroll
        for (int e = 0; e < 4; ++e) acc[f][e] = 0.0f;

    const int quad = lane >> 3, r8 = lane & 7;
    // A tile lane mapping: quads {m0-7,klo}{m8-15,klo}{m0-7,khi}{m8-15,khi}
    const int a_moff = (quad & 1) * 8 + r8;
    const int a_koff = (quad >> 1) * 16;       // bytes
    // B tile lane mapping: quads {n0-7,klo}{n0-7,khi}{n8-15,klo}{n8-15,khi}
    const int b_noff = (quad >> 1) * 8 + r8;
    const int b_koff = (quad & 1) * 16;        // bytes

#pragma unroll
    for (int kb = 0; kb < 4; ++kb) {
        uint32_t Ah[2][4], Al[2][4];
#pragma unroll
        for (int mb = 0; mb < 2; ++mb) {
            int row = wid * 32 + mb * 16 + a_moff;
            uint32_t off = SW128((uint32_t)(row * 128 + kb * 32 + a_koff));
            ldm4(Ah[mb], sb + SM_A_HI + off);
            ldm4(Al[mb], sb + SM_A_LO + off);
        }
#pragma unroll
        for (int nb = 0; nb < 4; ++nb) {   // covers n 16nb..16nb+15 (2 n8 frags)
            int n = 16 * nb + b_noff;
            uint32_t off = SW128((uint32_t)(n * 128 + kb * 32 + b_koff));
            uint32_t Bh[4], Bl[4];
            ldm4(Bh, sb + SM_B_HI + off);
            ldm4(Bl, sb + SM_B_LO + off);
#pragma unroll
            for (int h = 0; h < 2; ++h) {  // n8 frag within x4: regs 2h,2h+1
                int nf = 2 * nb + h;
#pragma unroll
                for (int mb = 0; mb < 2; ++mb) {
                    float* d = acc[mb * 8 + nf];
                    mma16816(d, Ah[mb], Bh[2 * h], Bh[2 * h + 1]);
                    mma16816(d, Ah[mb], Bl[2 * h], Bl[2 * h + 1]);
                    mma16816(d, Al[mb], Bh[2 * h], Bh[2 * h + 1]);
                }
            }
        }
    }
    __syncthreads();   // all ldmatrix reads done before staging overwrites A/B

    // ---- Phase 3: stage D to padded smem (17 f4 per strip), coalesced store ----
    {
        float* stage = (float*)(smem + SM_STAGE);
        const int g = lane >> 2, tig = lane & 3;
#pragma unroll
        for (int mb = 0; mb < 2; ++mb) {
#pragma unroll
            for (int nf = 0; nf < 8; ++nf) {
                const float* d = acc[mb * 8 + nf];
                int col = nf * 8 + 2 * tig;
                int r0 = wid * 32 + mb * 16 + g;
                *(float2*)(stage + r0 * 68 + col)       = make_float2(d[0], d[1]);
                *(float2*)(stage + (r0 + 8) * 68 + col) = make_float2(d[2], d[3]);
            }
        }
    }
    __syncthreads();
    {
        const float4* stage = (const float4*)(smem + SM_STAGE);
#pragma unroll
        for (int k = 0; k < 16; ++k)
            out4[base + k * THREADS + t] = stage[(8 * k + (t >> 4)) * 17 + (t & 15)];
    }
}

// ---- SIMT tail (rem strips; none on bench shape) ----
#define DCT_TABLE(CT)                                                                  \
    const float CT[8][8] = {                                                           \
        {0.353553391f,0.353553391f,0.353553391f,0.353553391f,                          \
         0.353553391f,0.353553391f,0.353553391f,0.353553391f},                         \
        {0.490392640f,0.415734806f,0.277785117f,0.097545161f,                          \
         -0.097545161f,-0.277785117f,-0.415734806f,-0.490392640f},                     \
        {0.461939766f,0.191341716f,-0.191341716f,-0.461939766f,                        \
         -0.461939766f,-0.191341716f,0.191341716f,0.461939766f},                       \
        {0.415734806f,-0.097545161f,-0.490392640f,-0.277785117f,                       \
         0.277785117f,0.490392640f,0.097545161f,-0.415734806f},                        \
        {0.353553391f,-0.353553391f,-0.353553391f,0.353553391f,                        \
         0.353553391f,-0.353553391f,-0.353553391f,0.353553391f},                       \
        {0.277785117f,-0.490392640f,0.097545161f,0.415734806f,                         \
         -0.415734806f,-0.097545161f,0.490392640f,-0.277785117f},                      \
        {0.191341716f,-0.461939766f,0.461939766f,-0.191341716f,                        \
         -0.191341716f,0.461939766f,-0.461939766f,0.191341716f},                       \
        {0.097545161f,-0.277785117f,0.415734806f,-0.490392640f,                        \
         0.490392640f,-0.415734806f,0.277785117f,-0.097545161f}};

__global__ void dct_tail_kernel(const float4* __restrict__ in4,
                                float4* __restrict__ out4,
                                int first_strip, int nstrips)
{
    int strip = first_strip + blockIdx.x * blockDim.x + threadIdx.x;
    if (strip >= nstrips) return;
    float x[64];
    const float4* ip = in4 + (size_t)strip * 16;
#pragma unroll
    for (int k = 0; k < 16; ++k) {
        float4 v = ip[k];
        x[4*k+0]=v.x; x[4*k+1]=v.y; x[4*k+2]=v.z; x[4*k+3]=v.w;
    }
    DCT_TABLE(CT);
#pragma unroll
    for (int u = 0; u < 8; ++u) {
        float tr[8];
#pragma unroll
        for (int j = 0; j < 8; ++j) {
            float a = x[u*8+0] * CT[0][j];
#pragma unroll
            for (int v = 1; v < 8; ++v) a = fmaf(x[u*8+v], CT[v][j], a);
            tr[j] = a;
        }
#pragma unroll
        for (int j = 0; j < 8; ++j) x[u*8+j] = tr[j];
    }
    float4* op = out4 + (size_t)strip * 16;
#pragma unroll
    for (int r = 0; r < 8; ++r) {
        float o[8];
#pragma unroll
        for (int j = 0; j < 8; ++j) {
            float a = x[0*8+j] * CT[0][r];
#pragma unroll
            for (int u = 1; u < 8; ++u) a = fmaf(x[u*8+j], CT[u][r], a);
            o[j] = a;
        }
        op[2*r+0] = make_float4(o[0],o[1],o[2],o[3]);
        op[2*r+1] = make_float4(o[4],o[5],o[6],o[7]);
    }
}

extern "C" void kernel_launch(void* const* d_in, const int* in_sizes, int n_in,
                              void* d_out, int out_size)
{
    const float4* in4  = (const float4*)d_in[0];  // (8,3,1024,1024) fp32
    const float*  Kmat = (const float*)d_in[1];   // (64,64) fp32
    float4* out4       = (float4*)d_out;

    prep_B_kernel<<<8, 512>>>(Kmat);

    int nstrips = in_sizes[0] / 64;               // 393216
    int ntiles  = nstrips / TILE_STRIPS;          // 3072
    if (ntiles > 0)
        dct_mma_kernel<<<ntiles, THREADS>>>(in4, out4);
    int rem = nstrips - ntiles * TILE_STRIPS;
    if (rem > 0)
        dct_tail_kernel<<<(rem + 127) / 128, 128>>>(in4, out4,
                                                    ntiles * TILE_STRIPS, nstrips);
}